// round 14
// baseline (speedup 1.0000x reference)
#include <cuda_runtime.h>
#include <cuda_fp16.h>
#include <math.h>
#include <cstdint>

#define CDIM 128
#define BDIM 8
#define NDIM 2048

// ------- GEMM: CTA m64 x n128, BK=64, 3 stages, 8 compute + 2 producer warps
#define NSTAGE 3
#define BK 64
#define NITER (NDIM / BK)          // 32
#define A_ROWP 72                  // halves per row (64 data + 8 pad) -> 144B stride
#define A_STB (64 * A_ROWP * 2)    // 9216 B per A stage
#define B_STB (136 * A_ROWP * 2)   // 19584 B per B stage (128 g + 1 w + 7 zero)
#define B_OFFB (NSTAGE * A_STB)    // 27648
#define DEN_OFFB (B_OFFB + NSTAGE * B_STB)   // 86400
#define SMEM_TOTAL (DEN_OFFB + 4 * 64 * 4)   // 87424 B -> 2 CTAs/SM
#define NTHR 320

// ---------------- device scratch ----------------
__device__ __half g_gT[BDIM * CDIM * NDIM];  // [b][c][j] = fp16(w*h)
__device__ __half g_w[BDIM * NDIM];          // [b][j]    = fp16(w)

// ---------------- helpers ----------------
__device__ __forceinline__ uint32_t smem_u32(const void* p) {
    uint32_t a;
    asm("{ .reg .u64 t; cvta.to.shared.u64 t, %1; cvt.u32.u64 %0, t; }" : "=r"(a) : "l"(p));
    return a;
}
__device__ __forceinline__ void cp16(uint32_t dst, const void* src) {
    asm volatile("cp.async.cg.shared.global [%0], [%1], 16;" :: "r"(dst), "l"(src));
}
#define CP_COMMIT() asm volatile("cp.async.commit_group;" ::: "memory")
#define CP_WAIT1()  asm volatile("cp.async.wait_group 1;" ::: "memory")

#define LDSM_X4(r0, r1, r2, r3, a) \
    asm volatile("ldmatrix.sync.aligned.m8n8.x4.shared.b16 {%0,%1,%2,%3}, [%4];" \
        : "=r"(r0), "=r"(r1), "=r"(r2), "=r"(r3) : "r"(a))
#define LDSM_X2(r0, r1, a) \
    asm volatile("ldmatrix.sync.aligned.m8n8.x2.shared.b16 {%0,%1}, [%2];" \
        : "=r"(r0), "=r"(r1) : "r"(a))

#define MMA_F16(d, a0, a1, a2, a3, b0, b1) \
    asm volatile("mma.sync.aligned.m16n8k16.row.col.f32.f16.f16.f32 " \
        "{%0,%1,%2,%3}, {%4,%5,%6,%7}, {%8,%9}, {%0,%1,%2,%3};" \
        : "+f"((d)[0]), "+f"((d)[1]), "+f"((d)[2]), "+f"((d)[3]) \
        : "r"(a0), "r"(a1), "r"(a2), "r"(a3), "r"(b0), "r"(b1))

// ---------------------------------------------------------------------------
// prep_g (same as R13): per 64-token tile, grid (32, 8), 256 thr.
// ---------------------------------------------------------------------------
#define PTOK 64
__global__ void __launch_bounds__(256)
prep_g_kernel(const float* __restrict__ h,
              const float* __restrict__ Ww,
              const float* __restrict__ Wb,
              const float* __restrict__ aw) {
    extern __shared__ float hs[];          // [64][129]
    __shared__ float vpart[8][128];
    __shared__ float spart[4][PTOK];
    __shared__ float awsh[CDIM];
    __shared__ float vsh[CDIM];
    __shared__ float wsh[PTOK];
    __shared__ float s0sh;

    const int b  = blockIdx.y;
    const int j0 = blockIdx.x * PTOK;
    const int tid = threadIdx.x;
    const int wid = tid >> 5, lid = tid & 31;

    if (tid < CDIM) awsh[tid] = aw[CDIM + tid];
    __syncthreads();

    {
        const int dp = wid, c4 = lid * 4;
        float4 acc4 = make_float4(0.f, 0.f, 0.f, 0.f);
#pragma unroll
        for (int q = 0; q < 16; q++) {
            int d = dp + q * 8;
            float a2 = awsh[d];
            float4 wv = *(const float4*)&Ww[(size_t)d * CDIM + c4];
            acc4.x = fmaf(wv.x, a2, acc4.x);
            acc4.y = fmaf(wv.y, a2, acc4.y);
            acc4.z = fmaf(wv.z, a2, acc4.z);
            acc4.w = fmaf(wv.w, a2, acc4.w);
        }
        *(float4*)&vpart[dp][c4] = acc4;
    }

    const float* hb = h + ((size_t)b * NDIM + j0) * CDIM;
#pragma unroll
    for (int l = 0; l < 8; l++) {
        int idx = tid + l * 256;
        int r = idx >> 5, c = (idx & 31) * 4;
        float4 v = *(const float4*)&hb[(size_t)r * CDIM + c];
        float* d = &hs[r * 129 + c];
        d[0] = v.x; d[1] = v.y; d[2] = v.z; d[3] = v.w;
    }
    __syncthreads();

    if (tid < CDIM) {
        float s = 0.f;
#pragma unroll
        for (int dp = 0; dp < 8; dp++) s += vpart[dp][tid];
        vsh[tid] = s;
    } else if (wid == 7) {
        float x = 0.f;
#pragma unroll
        for (int q = 0; q < 4; q++) {
            int d = lid + 32 * q;
            x += Wb[d] * awsh[d];
        }
#pragma unroll
        for (int o = 16; o > 0; o >>= 1) x += __shfl_down_sync(0xffffffffu, x, o);
        if (lid == 0) s0sh = x;
    }
    __syncthreads();

    {
        const int part = tid >> 6, j = tid & 63;
        const int c0 = part * 32;
        float p = 0.f;
#pragma unroll
        for (int q = 0; q < 32; q++)
            p = fmaf(hs[j * 129 + c0 + q], vsh[c0 + q], p);
        spart[part][j] = p;
    }
    __syncthreads();
    if (tid < PTOK)
        wsh[tid] = expf(spart[0][tid] + spart[1][tid] + spart[2][tid] +
                        spart[3][tid] + s0sh);
    __syncthreads();

    __half* Gb = g_gT + (size_t)b * CDIM * NDIM;
#pragma unroll
    for (int l = 0; l < 32; l++) {
        int idx = tid + l * 256;
        int c = idx >> 6, j = idx & 63;
        Gb[(size_t)c * NDIM + j0 + j] = __float2half_rn(wsh[j] * hs[j * 129 + c]);
    }
    if (tid < PTOK) g_w[(size_t)b * NDIM + j0 + tid] = __float2half_rn(wsh[tid]);
}

// ---------------------------------------------------------------------------
// Producer helpers (warps 8-9, ptid = tid-256 in 0..63)
// ---------------------------------------------------------------------------
__device__ __forceinline__ void prodA(uint32_t sb, int s, int it, int ptid,
                                      const float* __restrict__ Ab) {
    const float* src = Ab + it * BK;
    const uint32_t base = sb + s * A_STB;
    float4 buf[16];
#pragma unroll
    for (int l = 0; l < 16; l++) {
        int idx = ptid + l * 64;
        int r = idx >> 4, c = (idx & 15) * 4;
        buf[l] = *(const float4*)&src[(size_t)r * NDIM + c];
    }
#pragma unroll
    for (int l = 0; l < 16; l++) {
        int idx = ptid + l * 64;
        int r = idx >> 4, c = (idx & 15) * 4;
        __half2 h0 = __floats2half2_rn(buf[l].x, buf[l].y);
        __half2 h1 = __floats2half2_rn(buf[l].z, buf[l].w);
        asm volatile("st.shared.v2.b32 [%0], {%1,%2};"
                     :: "r"(base + (r * A_ROWP + c) * 2),
                        "r"(*(uint32_t*)&h0), "r"(*(uint32_t*)&h1) : "memory");
    }
}
__device__ __forceinline__ void prodB(uint32_t sb, int s, int it, int ptid,
                                      const __half* __restrict__ Gb,
                                      const __half* __restrict__ wb) {
    const int k0 = it * BK;
    const uint32_t base = sb + B_OFFB + s * B_STB;
#pragma unroll
    for (int l = 0; l < 16; l++) {
        int idx = ptid + l * 64;           // rows 0-127: 1024 chunks
        int r = idx >> 3, c = (idx & 7) * 8;
        cp16(base + (r * A_ROWP + c) * 2, Gb + (size_t)r * NDIM + k0 + c);
    }
    if (ptid < 8)                           // w row (row 128)
        cp16(base + (128 * A_ROWP + ptid * 8) * 2, wb + k0 + ptid * 8);
}

// ---------------------------------------------------------------------------
// GEMM: 320 thr = 8 compute warps (wm 0-1 x wn 0-3, warp m32 x n32)
//       + 2 producer warps.  Den-MMA spread: warp wn handles kk==wn only.
// ---------------------------------------------------------------------------
__global__ void __launch_bounds__(NTHR, 2)
attn_mma_kernel(const float* __restrict__ A, float* __restrict__ out) {
    extern __shared__ __align__(16) char smem[];
    const uint32_t sb = smem_u32(smem);
    const int tid = threadIdx.x;
    const int lane = tid & 31;
    const int g = lane >> 2, t = lane & 3;
    const int wid = tid >> 5;
    const bool isProd = (wid >= 8);
    const int wm = (wid >> 2) & 1, wn = wid & 3;
    const int b = blockIdx.y, m0 = blockIdx.x * 64;

    const float* __restrict__ Ab = A + (size_t)b * NDIM * NDIM + (size_t)m0 * NDIM;
    const __half* __restrict__ Gb = g_gT + (size_t)b * CDIM * NDIM;
    const __half* __restrict__ wb = g_w + (size_t)b * NDIM;

    // zero B pad rows (129..135) of all stages (all threads)
#pragma unroll
    for (int s = 0; s < NSTAGE; s++)
        for (int i = tid; i < 7 * A_ROWP / 2; i += NTHR)
            *(uint32_t*)(smem + B_OFFB + s * B_STB + 129 * A_ROWP * 2 + i * 4) = 0u;
    __syncthreads();

    // prologue: producers fill stages 0,1
    if (isProd) {
        const int ptid = tid - 256;
        prodA(sb, 0, 0, ptid, Ab);
        prodB(sb, 0, 0, ptid, Gb, wb); CP_COMMIT();
        prodA(sb, 1, 1, ptid, Ab);
        prodB(sb, 1, 1, ptid, Gb, wb); CP_COMMIT();
    }

    float acc[2][4][4];
#pragma unroll
    for (int mf = 0; mf < 2; mf++)
#pragma unroll
        for (int ch = 0; ch < 4; ch++)
#pragma unroll
            for (int q = 0; q < 4; q++) acc[mf][ch][q] = 0.f;
    float dacc[2][4];
#pragma unroll
    for (int mf = 0; mf < 2; mf++)
#pragma unroll
        for (int q = 0; q < 4; q++) dacc[mf][q] = 0.f;

    // ldmatrix lane addresses (stage-relative, bytes)
    const uint32_t aLane = ((lane & 15) * A_ROWP + (lane >> 4) * 8) * 2;
    const uint32_t bLane = aLane;
    const int l16 = lane & 15;
    const uint32_t dLane = (((128 + (l16 & 7)) * A_ROWP) + (l16 >> 3) * 8) * 2;

    int s = 0;
    for (int it = 0; it < NITER; ++it) {
        if (isProd) CP_WAIT1();     // stage s's cp group complete
        __syncthreads();            // stage s visible; stage (s+2)%3 free

        if (isProd) {
            const int ptid = tid - 256;
            const int ns = (s + 2 >= NSTAGE) ? s + 2 - NSTAGE : s + 2;
            if (it + 2 < NITER) {
                prodA(sb, ns, it + 2, ptid, Ab);
                prodB(sb, ns, it + 2, ptid, Gb, wb);
            }
            CP_COMMIT();
        } else {
            const uint32_t aBase = sb + s * A_STB + (wm * 32 * A_ROWP) * 2 + aLane;
            const uint32_t bBase = sb + B_OFFB + s * B_STB + (wn * 32 * A_ROWP) * 2 + bLane;
            const uint32_t dBase = sb + B_OFFB + s * B_STB + dLane;
#pragma unroll
            for (int kk = 0; kk < 4; kk++) {
                const uint32_t kb = kk * 32;   // 16 halves = 32 B
                uint32_t a0[2], a1[2], a2[2], a3[2];
#pragma unroll
                for (int mf = 0; mf < 2; mf++)
                    LDSM_X4(a0[mf], a1[mf], a2[mf], a3[mf],
                            aBase + mf * 16 * A_ROWP * 2 + kb);
                uint32_t b0[4], b1[4];
#pragma unroll
                for (int nh = 0; nh < 2; nh++) {
                    uint32_t r0, r1, r2, r3;
                    LDSM_X4(r0, r1, r2, r3, bBase + nh * 16 * A_ROWP * 2 + kb);
                    b0[nh * 2]     = r0; b1[nh * 2]     = r2;
                    b0[nh * 2 + 1] = r1; b1[nh * 2 + 1] = r3;
                }
#pragma unroll
                for (int mf = 0; mf < 2; mf++)
#pragma unroll
                    for (int ch = 0; ch < 4; ch++)
                        MMA_F16(acc[mf][ch], a0[mf], a1[mf], a2[mf], a3[mf],
                                b0[ch], b1[ch]);
                if (kk == wn) {     // den spread: one kk slice per wn warp
                    uint32_t w0, w1;
                    LDSM_X2(w0, w1, dBase + kb);
#pragma unroll
                    for (int mf = 0; mf < 2; mf++)
                        MMA_F16(dacc[mf], a0[mf], a1[mf], a2[mf], a3[mf], w0, w1);
                }
            }
        }
        s = (s + 1 >= NSTAGE) ? 0 : s + 1;
    }

    __syncthreads();

    // publish den partials: denS4[wn][row]; full den = sum over wn
    float* denS4 = (float*)(smem + DEN_OFFB);
    if (!isProd && t == 0) {
#pragma unroll
        for (int mf = 0; mf < 2; mf++) {
            denS4[wn * 64 + wm * 32 + mf * 16 + g]     = dacc[mf][0];
            denS4[wn * 64 + wm * 32 + mf * 16 + g + 8] = dacc[mf][2];
        }
    }
    __syncthreads();

    // scale + stage to smem stg[64][132]
    float* stg = (float*)smem;
    if (!isProd) {
#pragma unroll
        for (int mf = 0; mf < 2; mf++) {
            const int r0 = wm * 32 + mf * 16 + g;
            const int r1 = r0 + 8;
            const float inv0 = 1.0f / (denS4[r0] + denS4[64 + r0] +
                                       denS4[128 + r0] + denS4[192 + r0]);
            const float inv1 = 1.0f / (denS4[r1] + denS4[64 + r1] +
                                       denS4[128 + r1] + denS4[192 + r1]);
#pragma unroll
            for (int ch = 0; ch < 4; ch++) {
                const int col = wn * 32 + ch * 8 + 2 * t;
                *(float2*)&stg[r0 * 132 + col] =
                    make_float2(acc[mf][ch][0] * inv0, acc[mf][ch][1] * inv0);
                *(float2*)&stg[r1 * 132 + col] =
                    make_float2(acc[mf][ch][2] * inv1, acc[mf][ch][3] * inv1);
            }
        }
    }
    __syncthreads();

    float* __restrict__ ob = out + ((size_t)b * NDIM + m0) * CDIM;
    for (int idx = tid; idx < 2048; idx += NTHR) {
        int r = idx >> 5, c = idx & 31;
        *(float4*)&ob[r * CDIM + c * 4] = *(const float4*)&stg[r * 132 + c * 4];
    }
}

// ---------------------------------------------------------------------------
extern "C" void kernel_launch(void* const* d_in, const int* in_sizes, int n_in,
                              void* d_out, int out_size) {
    (void)in_sizes; (void)n_in; (void)out_size;
    const float* h  = (const float*)d_in[0];
    const float* A  = (const float*)d_in[1];
    const float* Ww = (const float*)d_in[2];
    const float* Wb = (const float*)d_in[3];
    const float* aw = (const float*)d_in[4];
    float* out = (float*)d_out;

    cudaFuncSetAttribute(prep_g_kernel,
                         cudaFuncAttributeMaxDynamicSharedMemorySize, PTOK * 129 * 4);
    cudaFuncSetAttribute(attn_mma_kernel,
                         cudaFuncAttributeMaxDynamicSharedMemorySize, SMEM_TOTAL);

    prep_g_kernel<<<dim3(NDIM / PTOK, BDIM), 256, PTOK * 129 * 4>>>(h, Ww, Wb, aw);
    attn_mma_kernel<<<dim3(NDIM / 64, BDIM), NTHR, SMEM_TOTAL>>>(A, out);
}

// round 16
// speedup vs baseline: 1.5881x; 1.5881x over previous
#include <cuda_runtime.h>
#include <cuda_fp16.h>
#include <math.h>
#include <cstdint>

#define CDIM 128
#define BDIM 8
#define NDIM 2048

// --- GEMM: CTA m64 x n128, BK=64, 4-stage ring, barrier every 2 iters ---
#define NSTAGE 4
#define BK 64
#define NITER (NDIM / BK)          // 32
#define A_ROWP 72                  // halves per row (64 data + 8 pad) -> 144B stride
#define A_STB (64 * A_ROWP * 2)    // 9216 B per A stage
#define B_STB (129 * A_ROWP * 2)   // 18576 B per B stage (128 g rows + 1 w row)
#define B_OFFB (NSTAGE * A_STB)    // 36864
#define DEN_OFFB (B_OFFB + NSTAGE * B_STB)   // 111168
#define SMEM_TOTAL (DEN_OFFB + 4 * 64 * 4)   // 112192 B -> 2 CTAs/SM

// ---------------- device scratch ----------------
__device__ __half g_gT[BDIM * CDIM * NDIM];  // [b][c][j] = fp16(w*h)
__device__ __half g_w[BDIM * NDIM];          // [b][j]    = fp16(w)

// ---------------- helpers ----------------
__device__ __forceinline__ uint32_t smem_u32(const void* p) {
    uint32_t a;
    asm("{ .reg .u64 t; cvta.to.shared.u64 t, %1; cvt.u32.u64 %0, t; }" : "=r"(a) : "l"(p));
    return a;
}
__device__ __forceinline__ void cp16(uint32_t dst, const void* src) {
    asm volatile("cp.async.cg.shared.global [%0], [%1], 16;" :: "r"(dst), "l"(src));
}
#define CP_COMMIT() asm volatile("cp.async.commit_group;" ::: "memory")
#define CP_WAIT0()  asm volatile("cp.async.wait_group 0;" ::: "memory")

#define LDSM_X4(r0, r1, r2, r3, a) \
    asm volatile("ldmatrix.sync.aligned.m8n8.x4.shared.b16 {%0,%1,%2,%3}, [%4];" \
        : "=r"(r0), "=r"(r1), "=r"(r2), "=r"(r3) : "r"(a))

#define MMA_F16(d, a0, a1, a2, a3, b0, b1) \
    asm volatile("mma.sync.aligned.m16n8k16.row.col.f32.f16.f16.f32 " \
        "{%0,%1,%2,%3}, {%4,%5,%6,%7}, {%8,%9}, {%0,%1,%2,%3};" \
        : "+f"((d)[0]), "+f"((d)[1]), "+f"((d)[2]), "+f"((d)[3]) \
        : "r"(a0), "r"(a1), "r"(a2), "r"(a3), "r"(b0), "r"(b1))

// ---------------------------------------------------------------------------
// prep_g (same as R13): per 64-token tile, grid (32, 8), 256 thr.
// ---------------------------------------------------------------------------
#define PTOK 64
__global__ void __launch_bounds__(256)
prep_g_kernel(const float* __restrict__ h,
              const float* __restrict__ Ww,
              const float* __restrict__ Wb,
              const float* __restrict__ aw) {
    extern __shared__ float hs[];          // [64][129]
    __shared__ float vpart[8][128];
    __shared__ float spart[4][PTOK];
    __shared__ float awsh[CDIM];
    __shared__ float vsh[CDIM];
    __shared__ float wsh[PTOK];
    __shared__ float s0sh;

    const int b  = blockIdx.y;
    const int j0 = blockIdx.x * PTOK;
    const int tid = threadIdx.x;
    const int wid = tid >> 5, lid = tid & 31;

    if (tid < CDIM) awsh[tid] = aw[CDIM + tid];
    __syncthreads();

    {
        const int dp = wid, c4 = lid * 4;
        float4 acc4 = make_float4(0.f, 0.f, 0.f, 0.f);
#pragma unroll
        for (int q = 0; q < 16; q++) {
            int d = dp + q * 8;
            float a2 = awsh[d];
            float4 wv = *(const float4*)&Ww[(size_t)d * CDIM + c4];
            acc4.x = fmaf(wv.x, a2, acc4.x);
            acc4.y = fmaf(wv.y, a2, acc4.y);
            acc4.z = fmaf(wv.z, a2, acc4.z);
            acc4.w = fmaf(wv.w, a2, acc4.w);
        }
        *(float4*)&vpart[dp][c4] = acc4;
    }

    const float* hb = h + ((size_t)b * NDIM + j0) * CDIM;
#pragma unroll
    for (int l = 0; l < 8; l++) {
        int idx = tid + l * 256;
        int r = idx >> 5, c = (idx & 31) * 4;
        float4 v = *(const float4*)&hb[(size_t)r * CDIM + c];
        float* d = &hs[r * 129 + c];
        d[0] = v.x; d[1] = v.y; d[2] = v.z; d[3] = v.w;
    }
    __syncthreads();

    if (tid < CDIM) {
        float s = 0.f;
#pragma unroll
        for (int dp = 0; dp < 8; dp++) s += vpart[dp][tid];
        vsh[tid] = s;
    } else if (wid == 7) {
        float x = 0.f;
#pragma unroll
        for (int q = 0; q < 4; q++) {
            int d = lid + 32 * q;
            x += Wb[d] * awsh[d];
        }
#pragma unroll
        for (int o = 16; o > 0; o >>= 1) x += __shfl_down_sync(0xffffffffu, x, o);
        if (lid == 0) s0sh = x;
    }
    __syncthreads();

    {
        const int part = tid >> 6, j = tid & 63;
        const int c0 = part * 32;
        float p = 0.f;
#pragma unroll
        for (int q = 0; q < 32; q++)
            p = fmaf(hs[j * 129 + c0 + q], vsh[c0 + q], p);
        spart[part][j] = p;
    }
    __syncthreads();
    if (tid < PTOK)
        wsh[tid] = expf(spart[0][tid] + spart[1][tid] + spart[2][tid] +
                        spart[3][tid] + s0sh);
    __syncthreads();

    __half* Gb = g_gT + (size_t)b * CDIM * NDIM;
#pragma unroll
    for (int l = 0; l < 32; l++) {
        int idx = tid + l * 256;
        int c = idx >> 6, j = idx & 63;
        Gb[(size_t)c * NDIM + j0 + j] = __float2half_rn(wsh[j] * hs[j * 129 + c]);
    }
    if (tid < PTOK) g_w[(size_t)b * NDIM + j0 + tid] = __float2half_rn(wsh[tid]);
}

// ---------------------------------------------------------------------------
// GEMM loaders
// ---------------------------------------------------------------------------
__device__ __forceinline__ void ldgA(const float* __restrict__ Ab, int it, int tid,
                                     float4 (&ra)[4]) {
    const float* src = Ab + it * BK;
#pragma unroll
    for (int l = 0; l < 4; l++) {
        int idx = tid + l * 256;           // 1024 float4 per stage
        int r = idx >> 4, c = (idx & 15) * 4;
        ra[l] = *(const float4*)&src[(size_t)r * NDIM + c];
    }
}
__device__ __forceinline__ void stsA(uint32_t sb, int s, int tid, const float4 (&ra)[4]) {
    const uint32_t base = sb + s * A_STB;
#pragma unroll
    for (int l = 0; l < 4; l++) {
        int idx = tid + l * 256;
        int r = idx >> 4, c = (idx & 15) * 4;
        __half2 h0 = __floats2half2_rn(ra[l].x, ra[l].y);
        __half2 h1 = __floats2half2_rn(ra[l].z, ra[l].w);
        asm volatile("st.shared.v2.b32 [%0], {%1,%2};"
                     :: "r"(base + (r * A_ROWP + c) * 2),
                        "r"(*(uint32_t*)&h0), "r"(*(uint32_t*)&h1) : "memory");
    }
}
__device__ __forceinline__ void cpB(uint32_t sb, int s, int it, int tid,
                                    const __half* __restrict__ Gb,
                                    const __half* __restrict__ wb) {
    const int k0 = it * BK;
    const uint32_t base = sb + B_OFFB + s * B_STB;
#pragma unroll
    for (int l = 0; l < 4; l++) {
        int idx = tid + l * 256;           // rows 0-127: 1024 chunks
        int r = idx >> 3, c = (idx & 7) * 8;
        cp16(base + (r * A_ROWP + c) * 2, Gb + (size_t)r * NDIM + k0 + c);
    }
    if (tid < 8)                            // w row (row 128): 8 chunks
        cp16(base + (128 * A_ROWP + tid * 8) * 2, wb + k0 + tid * 8);
}

// One stage of compute (macro so locals/acc bind directly)
#define COMPUTE_STAGE(S)                                                        \
{                                                                               \
    const uint32_t aBase = sb + (S) * A_STB + (wm * 32 * A_ROWP) * 2 + aLane;   \
    const uint32_t bBase = sb + B_OFFB + (S) * B_STB + (wn * 32 * A_ROWP) * 2 + bLane; \
    const uint32_t wRow  = sb + B_OFFB + (S) * B_STB + (128 * A_ROWP) * 2;      \
    _Pragma("unroll")                                                           \
    for (int kk = 0; kk < 4; kk++) {                                            \
        const uint32_t kb = kk * 32;   /* byte offset: 16 halves per kk */      \
        uint32_t a0[2], a1[2], a2[2], a3[2];                                    \
        _Pragma("unroll")                                                       \
        for (int mf = 0; mf < 2; mf++)                                          \
            LDSM_X4(a0[mf], a1[mf], a2[mf], a3[mf],                             \
                    aBase + mf * 16 * A_ROWP * 2 + kb);                         \
        uint32_t b0[4], b1[4];                                                  \
        _Pragma("unroll")                                                       \
        for (int nh = 0; nh < 2; nh++) {                                        \
            uint32_t r0, r1, r2, r3;                                            \
            LDSM_X4(r0, r1, r2, r3, bBase + nh * 16 * A_ROWP * 2 + kb);         \
            b0[nh * 2]     = r0; b1[nh * 2]     = r2;                           \
            b0[nh * 2 + 1] = r1; b1[nh * 2 + 1] = r3;                           \
        }                                                                       \
        _Pragma("unroll")                                                       \
        for (int mf = 0; mf < 2; mf++)                                          \
            _Pragma("unroll")                                                   \
            for (int ch = 0; ch < 4; ch++)                                      \
                MMA_F16(acc[mf][ch], a0[mf], a1[mf], a2[mf], a3[mf],            \
                        b0[ch], b1[ch]);                                        \
        if (kk == wn) {           /* den spread: one kk slice per wn warp */    \
            uint32_t w0 = 0u, w1 = 0u;                                          \
            if (g == 0) {  /* b0: k = kk*16 + 2t -> byte kb + 4t; b1: +16B */   \
                const uint32_t woff = wRow + kb + 4 * t;                        \
                asm volatile("ld.shared.b32 %0, [%1];" : "=r"(w0) : "r"(woff)); \
                asm volatile("ld.shared.b32 %0, [%1];" : "=r"(w1) : "r"(woff + 16)); \
            }                                                                   \
            _Pragma("unroll")                                                   \
            for (int mf = 0; mf < 2; mf++)                                      \
                MMA_F16(dacc[mf], a0[mf], a1[mf], a2[mf], a3[mf], w0, w1);      \
        }                                                                       \
    }                                                                           \
}

// ---------------------------------------------------------------------------
// GEMM: 256 thr = 8 warps (wm 0-1 x wn 0-3), warp tile m32 x n32.
// Barrier once per 2 iterations; loads interleaved between compute halves.
// ---------------------------------------------------------------------------
__global__ void __launch_bounds__(256, 2)
attn_mma_kernel(const float* __restrict__ A, float* __restrict__ out) {
    extern __shared__ __align__(16) char smem[];
    const uint32_t sb = smem_u32(smem);
    const int tid = threadIdx.x;
    const int lane = tid & 31;
    const int g = lane >> 2, t = lane & 3;
    const int wid = tid >> 5;
    const int wm = wid >> 2, wn = wid & 3;
    const int b = blockIdx.y, m0 = blockIdx.x * 64;

    const float* __restrict__ Ab = A + (size_t)b * NDIM * NDIM + (size_t)m0 * NDIM;
    const __half* __restrict__ Gb = g_gT + (size_t)b * CDIM * NDIM;
    const __half* __restrict__ wb = g_w + (size_t)b * NDIM;

    float acc[2][4][4];
#pragma unroll
    for (int mf = 0; mf < 2; mf++)
#pragma unroll
        for (int ch = 0; ch < 4; ch++)
#pragma unroll
            for (int q = 0; q < 4; q++) acc[mf][ch][q] = 0.f;
    float dacc[2][4];
#pragma unroll
    for (int mf = 0; mf < 2; mf++)
#pragma unroll
        for (int q = 0; q < 4; q++) dacc[mf][q] = 0.f;

    // ldmatrix lane addresses (stage-relative, bytes)
    const uint32_t aLane = ((lane & 15) * A_ROWP + (lane >> 4) * 8) * 2;
    const uint32_t bLane = aLane;

    // prologue: stages 0,1 staged; A(2) in regs
    float4 ra[4];
    ldgA(Ab, 0, tid, ra); stsA(sb, 0, tid, ra);
    cpB(sb, 0, 0, tid, Gb, wb); CP_COMMIT();
    ldgA(Ab, 1, tid, ra); stsA(sb, 1, tid, ra);
    cpB(sb, 1, 1, tid, Gb, wb); CP_COMMIT();
    ldgA(Ab, 2, tid, ra);

    for (int i = 0; i < NITER; i += 2) {
        CP_WAIT0();
        __syncthreads();            // stages i, i+1 visible; stages i+2, i+3 slots free

        if (i + 2 < NITER) {
            stsA(sb, (i + 2) & 3, tid, ra);           // A(i+2) from regs
            cpB(sb, (i + 2) & 3, i + 2, tid, Gb, wb);
            CP_COMMIT();
            ldgA(Ab, i + 3, tid, ra);                 // A(i+3) -> regs
        }

        COMPUTE_STAGE(i & 3);

        if (i + 3 < NITER) {
            stsA(sb, (i + 3) & 3, tid, ra);           // LDG had a full stage to land
            cpB(sb, (i + 3) & 3, i + 3, tid, Gb, wb);
            CP_COMMIT();
            ldgA(Ab, i + 4, tid, ra);                 // A(i+4) for next period
        }

        COMPUTE_STAGE((i + 1) & 3);
    }

    __syncthreads();

    // publish den partials: denS4[wn][row]; full den = sum over wn
    float* denS4 = (float*)(smem + DEN_OFFB);
    if (t == 0) {
#pragma unroll
        for (int mf = 0; mf < 2; mf++) {
            denS4[wn * 64 + wm * 32 + mf * 16 + g]     = dacc[mf][0];
            denS4[wn * 64 + wm * 32 + mf * 16 + g + 8] = dacc[mf][2];
        }
    }
    __syncthreads();

    // scale + stage to smem stg[64][132]
    float* stg = (float*)smem;
#pragma unroll
    for (int mf = 0; mf < 2; mf++) {
        const int r0 = wm * 32 + mf * 16 + g;
        const int r1 = r0 + 8;
        const float inv0 = 1.0f / (denS4[r0] + denS4[64 + r0] +
                                   denS4[128 + r0] + denS4[192 + r0]);
        const float inv1 = 1.0f / (denS4[r1] + denS4[64 + r1] +
                                   denS4[128 + r1] + denS4[192 + r1]);
#pragma unroll
        for (int ch = 0; ch < 4; ch++) {
            const int col = wn * 32 + ch * 8 + 2 * t;
            *(float2*)&stg[r0 * 132 + col] =
                make_float2(acc[mf][ch][0] * inv0, acc[mf][ch][1] * inv0);
            *(float2*)&stg[r1 * 132 + col] =
                make_float2(acc[mf][ch][2] * inv1, acc[mf][ch][3] * inv1);
        }
    }
    __syncthreads();

    float* __restrict__ ob = out + ((size_t)b * NDIM + m0) * CDIM;
#pragma unroll
    for (int l = 0; l < 8; l++) {
        int idx = tid + l * 256;           // 2048 float4
        int r = idx >> 5, c = idx & 31;
        *(float4*)&ob[r * CDIM + c * 4] = *(const float4*)&stg[r * 132 + c * 4];
    }
}

// ---------------------------------------------------------------------------
extern "C" void kernel_launch(void* const* d_in, const int* in_sizes, int n_in,
                              void* d_out, int out_size) {
    (void)in_sizes; (void)n_in; (void)out_size;
    const float* h  = (const float*)d_in[0];
    const float* A  = (const float*)d_in[1];
    const float* Ww = (const float*)d_in[2];
    const float* Wb = (const float*)d_in[3];
    const float* aw = (const float*)d_in[4];
    float* out = (float*)d_out;

    cudaFuncSetAttribute(prep_g_kernel,
                         cudaFuncAttributeMaxDynamicSharedMemorySize, PTOK * 129 * 4);
    cudaFuncSetAttribute(attn_mma_kernel,
                         cudaFuncAttributeMaxDynamicSharedMemorySize, SMEM_TOTAL);

    prep_g_kernel<<<dim3(NDIM / PTOK, BDIM), 256, PTOK * 129 * 4>>>(h, Ww, Wb, aw);
    attn_mma_kernel<<<dim3(NDIM / 64, BDIM), 256, SMEM_TOTAL>>>(A, out);
}